// round 1
// baseline (speedup 1.0000x reference)
#include <cuda_runtime.h>
#include <math.h>

// Problem constants
#define Bb   2
#define Nn   2048
#define Din  1024
#define Dout 1024
#define Hh   16
#define HDd  64

// Scratch (allocation-free rule: __device__ globals)
__device__ float g_q[Bb * Hh * Nn * HDd];     // [B,H,N,HD]
__device__ float g_k[Bb * Hh * Nn * HDd];
__device__ float g_v[Bb * Hh * Nn * HDd];
__device__ float g_ctx[Bb * Nn * Dout];       // [B,N,D] row-major

// ---------------------------------------------------------------------------
// 128x128x8 SGEMM body, 256 threads, 8x8 microtile per thread.
// A: [M,K] row-major, W: [K,Ncols] row-major. Shapes are fixed multiples.
// ---------------------------------------------------------------------------

// QKV projection: x[4096,1024] @ {Wq,Wk,Wv}[1024,1024] -> g_{q,k,v} in [B,H,N,HD]
__global__ __launch_bounds__(256) void qkv_kernel(
    const float* __restrict__ x,
    const float* __restrict__ Wq,
    const float* __restrict__ Wk,
    const float* __restrict__ Wv)
{
    __shared__ float As[8][128];
    __shared__ float Bs[8][128];

    const float* W   = (blockIdx.z == 0) ? Wq : (blockIdx.z == 1) ? Wk : Wv;
    float*       out = (blockIdx.z == 0) ? g_q : (blockIdx.z == 1) ? g_k : g_v;

    const int tid  = threadIdx.x;
    const int row0 = blockIdx.y * 128;
    const int col0 = blockIdx.x * 128;

    const int ar = tid >> 1;          // 0..127
    const int ac = (tid & 1) * 4;     // 0 or 4
    const int br = tid >> 5;          // 0..7
    const int bc = (tid & 31) * 4;    // 0..124

    const int ty = tid >> 4;          // 0..15
    const int tx = tid & 15;          // 0..15

    float acc[8][8];
#pragma unroll
    for (int i = 0; i < 8; i++)
#pragma unroll
        for (int j = 0; j < 8; j++) acc[i][j] = 0.f;

    for (int k0 = 0; k0 < Din; k0 += 8) {
        float4 av = *(const float4*)&x[(row0 + ar) * Din + k0 + ac];
        As[ac + 0][ar] = av.x;
        As[ac + 1][ar] = av.y;
        As[ac + 2][ar] = av.z;
        As[ac + 3][ar] = av.w;
        *(float4*)&Bs[br][bc] = *(const float4*)&W[(k0 + br) * Dout + col0 + bc];
        __syncthreads();

#pragma unroll
        for (int k = 0; k < 8; k++) {
            float4 a0 = *(float4*)&As[k][ty * 8];
            float4 a1 = *(float4*)&As[k][ty * 8 + 4];
            float4 b0 = *(float4*)&Bs[k][tx * 8];
            float4 b1 = *(float4*)&Bs[k][tx * 8 + 4];
            float a[8] = {a0.x, a0.y, a0.z, a0.w, a1.x, a1.y, a1.z, a1.w};
            float b[8] = {b0.x, b0.y, b0.z, b0.w, b1.x, b1.y, b1.z, b1.w};
#pragma unroll
            for (int i = 0; i < 8; i++)
#pragma unroll
                for (int j = 0; j < 8; j++) acc[i][j] = fmaf(a[i], b[j], acc[i][j]);
        }
        __syncthreads();
    }

    // Epilogue: scatter into [B,H,N,HD]
#pragma unroll
    for (int i = 0; i < 8; i++) {
        int gm = row0 + ty * 8 + i;
        int b  = gm >> 11;            // /2048
        int n  = gm & 2047;
#pragma unroll
        for (int j = 0; j < 8; j++) {
            int col = col0 + tx * 8 + j;
            int h   = col >> 6;
            int hd  = col & 63;
            out[((b * Hh + h) * Nn + n) * HDd + hd] = acc[i][j];
        }
    }
}

// Output projection: g_ctx[4096,1024] @ Wo[1024,1024] + bo -> d_out row-major
__global__ __launch_bounds__(256) void out_proj_kernel(
    const float* __restrict__ Wo,
    const float* __restrict__ bo,
    float* __restrict__ out)
{
    __shared__ float As[8][128];
    __shared__ float Bs[8][128];

    const int tid  = threadIdx.x;
    const int row0 = blockIdx.y * 128;
    const int col0 = blockIdx.x * 128;

    const int ar = tid >> 1;
    const int ac = (tid & 1) * 4;
    const int br = tid >> 5;
    const int bc = (tid & 31) * 4;
    const int ty = tid >> 4;
    const int tx = tid & 15;

    float acc[8][8];
#pragma unroll
    for (int i = 0; i < 8; i++)
#pragma unroll
        for (int j = 0; j < 8; j++) acc[i][j] = 0.f;

    for (int k0 = 0; k0 < Dout; k0 += 8) {
        float4 av = *(const float4*)&g_ctx[(row0 + ar) * Dout + k0 + ac];
        As[ac + 0][ar] = av.x;
        As[ac + 1][ar] = av.y;
        As[ac + 2][ar] = av.z;
        As[ac + 3][ar] = av.w;
        *(float4*)&Bs[br][bc] = *(const float4*)&Wo[(k0 + br) * Dout + col0 + bc];
        __syncthreads();

#pragma unroll
        for (int k = 0; k < 8; k++) {
            float4 a0 = *(float4*)&As[k][ty * 8];
            float4 a1 = *(float4*)&As[k][ty * 8 + 4];
            float4 b0 = *(float4*)&Bs[k][tx * 8];
            float4 b1 = *(float4*)&Bs[k][tx * 8 + 4];
            float a[8] = {a0.x, a0.y, a0.z, a0.w, a1.x, a1.y, a1.z, a1.w};
            float b[8] = {b0.x, b0.y, b0.z, b0.w, b1.x, b1.y, b1.z, b1.w};
#pragma unroll
            for (int i = 0; i < 8; i++)
#pragma unroll
                for (int j = 0; j < 8; j++) acc[i][j] = fmaf(a[i], b[j], acc[i][j]);
        }
        __syncthreads();
    }

#pragma unroll
    for (int i = 0; i < 8; i++) {
        int gm = row0 + ty * 8 + i;
#pragma unroll
        for (int j = 0; j < 8; j++) {
            int col = col0 + tx * 8 + j;
            out[gm * Dout + col] = acc[i][j] + bo[col];
        }
    }
}

// ---------------------------------------------------------------------------
// Flash attention (fp32, causal). One block = (qblock of 64) x head x batch.
// 256 threads, each owns a 4x4 tile of the 64x64 S / O blocks.
// ---------------------------------------------------------------------------
// smem layout (floats):
//   Qst [64k][68]  @ 0       (Q transposed: Qst[k][r], scaled by 1/sqrt(HD))
//   Kst [64k][68]  @ 4352    (K transposed: Kst[k][c])
//   Vs  [64r][64]  @ 8704    (V natural: Vs[key][c])
//   Ss  [64r][65]  @ 12800   (scores / probs)
//   m   [64]       @ 16960
//   l   [64]       @ 17024
//   rs  [64]       @ 17088
#define FLASH_SMEM_FLOATS 17152
#define FLASH_SMEM_BYTES  (FLASH_SMEM_FLOATS * 4)

__global__ __launch_bounds__(256) void flash_kernel()
{
    extern __shared__ float sm[];
    float* Qst  = sm;
    float* Kst  = sm + 4352;
    float* Vs   = sm + 8704;
    float* Ss   = sm + 12800;
    float* mrow = sm + 16960;
    float* lrow = sm + 17024;
    float* rsc  = sm + 17088;

    const int tid = threadIdx.x;
    const int qb  = blockIdx.x;
    const int h   = blockIdx.y;
    const int b   = blockIdx.z;

    const float* Qp = g_q + (size_t)((b * Hh + h) * Nn + qb * 64) * HDd;
    const float* Kp = g_k + (size_t)(b * Hh + h) * Nn * HDd;
    const float* Vp = g_v + (size_t)(b * Hh + h) * Nn * HDd;

    const int lr = tid >> 4;         // 0..15 (row within load rep)
    const int lc = (tid & 15) * 4;   // 0..60 (col, float4)

    const float sm_scale = 0.125f;   // 1/sqrt(64)

    // Load Q (transposed, pre-scaled)
#pragma unroll
    for (int rep = 0; rep < 4; rep++) {
        int r = lr + rep * 16;
        float4 v = *(const float4*)&Qp[r * HDd + lc];
        Qst[(lc + 0) * 68 + r] = v.x * sm_scale;
        Qst[(lc + 1) * 68 + r] = v.y * sm_scale;
        Qst[(lc + 2) * 68 + r] = v.z * sm_scale;
        Qst[(lc + 3) * 68 + r] = v.w * sm_scale;
    }
    if (tid < 64) { mrow[tid] = -INFINITY; lrow[tid] = 0.f; }

    const int ty = tid >> 4;   // 0..15 -> rows ty*4..ty*4+3
    const int tx = tid & 15;   // 0..15 -> cols tx*4..tx*4+3
    const int r0 = ty * 4;
    const int c0 = tx * 4;

    float acc[4][4];
#pragma unroll
    for (int i = 0; i < 4; i++)
#pragma unroll
        for (int j = 0; j < 4; j++) acc[i][j] = 0.f;

    __syncthreads();

    for (int kb = 0; kb <= qb; kb++) {
        // Load K (transposed) and V (natural)
#pragma unroll
        for (int rep = 0; rep < 4; rep++) {
            int r = lr + rep * 16;
            float4 kv = *(const float4*)&Kp[(kb * 64 + r) * HDd + lc];
            Kst[(lc + 0) * 68 + r] = kv.x;
            Kst[(lc + 1) * 68 + r] = kv.y;
            Kst[(lc + 2) * 68 + r] = kv.z;
            Kst[(lc + 3) * 68 + r] = kv.w;
            *(float4*)&Vs[r * 64 + lc] = *(const float4*)&Vp[(kb * 64 + r) * HDd + lc];
        }
        __syncthreads();

        // S = Q K^T (4x4 per thread)
        float sacc[4][4];
#pragma unroll
        for (int i = 0; i < 4; i++)
#pragma unroll
            for (int j = 0; j < 4; j++) sacc[i][j] = 0.f;

#pragma unroll 8
        for (int k = 0; k < 64; k++) {
            float4 a = *(float4*)&Qst[k * 68 + r0];
            float4 bb = *(float4*)&Kst[k * 68 + c0];
            float av[4] = {a.x, a.y, a.z, a.w};
            float bv[4] = {bb.x, bb.y, bb.z, bb.w};
#pragma unroll
            for (int i = 0; i < 4; i++)
#pragma unroll
                for (int j = 0; j < 4; j++) sacc[i][j] = fmaf(av[i], bv[j], sacc[i][j]);
        }

        // Causal mask on the diagonal block, write to Ss
        const bool diag = (kb == qb);
#pragma unroll
        for (int i = 0; i < 4; i++)
#pragma unroll
            for (int j = 0; j < 4; j++) {
                float s = sacc[i][j];
                if (diag && (c0 + j > r0 + i)) s = -1e30f;
                Ss[(r0 + i) * 65 + (c0 + j)] = s;
            }
        __syncthreads();

        // Online softmax per row (first 64 threads)
        if (tid < 64) {
            const int base = tid * 65;
            float mx = -1e30f;
#pragma unroll 8
            for (int j = 0; j < 64; j++) mx = fmaxf(mx, Ss[base + j]);
            float mnew = fmaxf(mrow[tid], mx);
            float sc   = __expf(mrow[tid] - mnew);
            float s    = 0.f;
#pragma unroll 8
            for (int j = 0; j < 64; j++) {
                float p = __expf(Ss[base + j] - mnew);
                Ss[base + j] = p;
                s += p;
            }
            lrow[tid] = lrow[tid] * sc + s;
            rsc[tid]  = sc;
            mrow[tid] = mnew;
        }
        __syncthreads();

        // Rescale accumulator, then O += P @ V
#pragma unroll
        for (int i = 0; i < 4; i++) {
            float sc = rsc[r0 + i];
#pragma unroll
            for (int j = 0; j < 4; j++) acc[i][j] *= sc;
        }
#pragma unroll 8
        for (int j = 0; j < 64; j++) {
            float4 vv = *(float4*)&Vs[j * 64 + c0];
            float vvv[4] = {vv.x, vv.y, vv.z, vv.w};
#pragma unroll
            for (int i = 0; i < 4; i++) {
                float p = Ss[(r0 + i) * 65 + j];
#pragma unroll
                for (int jj = 0; jj < 4; jj++) acc[i][jj] = fmaf(p, vvv[jj], acc[i][jj]);
            }
        }
        __syncthreads();
    }

    // Normalize and write ctx in [B,N,D] (contiguous for the output GEMM)
#pragma unroll
    for (int i = 0; i < 4; i++) {
        float inv = 1.f / lrow[r0 + i];
        int n = qb * 64 + r0 + i;
        float4 o;
        o.x = acc[i][0] * inv;
        o.y = acc[i][1] * inv;
        o.z = acc[i][2] * inv;
        o.w = acc[i][3] * inv;
        *(float4*)&g_ctx[(size_t)(b * Nn + n) * Dout + h * 64 + c0] = o;
    }
}

// ---------------------------------------------------------------------------
extern "C" void kernel_launch(void* const* d_in, const int* in_sizes, int n_in,
                              void* d_out, int out_size)
{
    const float* x  = (const float*)d_in[0];
    const float* Wq = (const float*)d_in[1];
    const float* Wk = (const float*)d_in[2];
    const float* Wv = (const float*)d_in[3];
    const float* Wo = (const float*)d_in[4];
    const float* bo = (const float*)d_in[5];
    float* out = (float*)d_out;

    cudaFuncSetAttribute(flash_kernel, cudaFuncAttributeMaxDynamicSharedMemorySize,
                         FLASH_SMEM_BYTES);

    dim3 gemm_grid(Dout / 128, (Bb * Nn) / 128, 3);
    qkv_kernel<<<gemm_grid, 256>>>(x, Wq, Wk, Wv);

    dim3 flash_grid(Nn / 64, Hh, Bb);
    flash_kernel<<<flash_grid, 256, FLASH_SMEM_BYTES>>>();

    dim3 out_grid(Dout / 128, (Bb * Nn) / 128);
    out_proj_kernel<<<out_grid, 256>>>(Wo, bo, out);
}

// round 11
// speedup vs baseline: 1.0114x; 1.0114x over previous
#include <cuda_runtime.h>
#include <math.h>

// Problem constants
#define Bb   2
#define Nn   2048
#define Din  1024
#define Dout 1024
#define Hh   16
#define HDd  64

// Scratch (allocation-free rule: __device__ globals) — identical set to R1
__device__ float g_q[Bb * Hh * Nn * HDd];     // [B,H,N,HD]
__device__ float g_k[Bb * Hh * Nn * HDd];
__device__ float g_v[Bb * Hh * Nn * HDd];
__device__ float g_ctx[Bb * Nn * Dout];       // [B,N,D] row-major

// ---------------------------------------------------------------------------
// 128x128x8 SGEMM body, 256 threads, 8x8 microtile per thread. (R1 verbatim)
// ---------------------------------------------------------------------------
__global__ __launch_bounds__(256) void qkv_kernel(
    const float* __restrict__ x,
    const float* __restrict__ Wq,
    const float* __restrict__ Wk,
    const float* __restrict__ Wv)
{
    __shared__ float As[8][128];
    __shared__ float Bs[8][128];

    const float* W   = (blockIdx.z == 0) ? Wq : (blockIdx.z == 1) ? Wk : Wv;
    float*       out = (blockIdx.z == 0) ? g_q : (blockIdx.z == 1) ? g_k : g_v;

    const int tid  = threadIdx.x;
    const int row0 = blockIdx.y * 128;
    const int col0 = blockIdx.x * 128;

    const int ar = tid >> 1;
    const int ac = (tid & 1) * 4;
    const int br = tid >> 5;
    const int bc = (tid & 31) * 4;
    const int ty = tid >> 4;
    const int tx = tid & 15;

    float acc[8][8];
#pragma unroll
    for (int i = 0; i < 8; i++)
#pragma unroll
        for (int j = 0; j < 8; j++) acc[i][j] = 0.f;

    for (int k0 = 0; k0 < Din; k0 += 8) {
        float4 av = *(const float4*)&x[(row0 + ar) * Din + k0 + ac];
        As[ac + 0][ar] = av.x;
        As[ac + 1][ar] = av.y;
        As[ac + 2][ar] = av.z;
        As[ac + 3][ar] = av.w;
        *(float4*)&Bs[br][bc] = *(const float4*)&W[(k0 + br) * Dout + col0 + bc];
        __syncthreads();

#pragma unroll
        for (int k = 0; k < 8; k++) {
            float4 a0 = *(float4*)&As[k][ty * 8];
            float4 a1 = *(float4*)&As[k][ty * 8 + 4];
            float4 b0 = *(float4*)&Bs[k][tx * 8];
            float4 b1 = *(float4*)&Bs[k][tx * 8 + 4];
            float a[8] = {a0.x, a0.y, a0.z, a0.w, a1.x, a1.y, a1.z, a1.w};
            float b[8] = {b0.x, b0.y, b0.z, b0.w, b1.x, b1.y, b1.z, b1.w};
#pragma unroll
            for (int i = 0; i < 8; i++)
#pragma unroll
                for (int j = 0; j < 8; j++) acc[i][j] = fmaf(a[i], b[j], acc[i][j]);
        }
        __syncthreads();
    }

#pragma unroll
    for (int i = 0; i < 8; i++) {
        int gm = row0 + ty * 8 + i;
        int b  = gm >> 11;
        int n  = gm & 2047;
#pragma unroll
        for (int j = 0; j < 8; j++) {
            int col = col0 + tx * 8 + j;
            int h   = col >> 6;
            int hd  = col & 63;
            out[((b * Hh + h) * Nn + n) * HDd + hd] = acc[i][j];
        }
    }
}

__global__ __launch_bounds__(256) void out_proj_kernel(
    const float* __restrict__ Wo,
    const float* __restrict__ bo,
    float* __restrict__ out)
{
    __shared__ float As[8][128];
    __shared__ float Bs[8][128];

    const int tid  = threadIdx.x;
    const int row0 = blockIdx.y * 128;
    const int col0 = blockIdx.x * 128;

    const int ar = tid >> 1;
    const int ac = (tid & 1) * 4;
    const int br = tid >> 5;
    const int bc = (tid & 31) * 4;
    const int ty = tid >> 4;
    const int tx = tid & 15;

    float acc[8][8];
#pragma unroll
    for (int i = 0; i < 8; i++)
#pragma unroll
        for (int j = 0; j < 8; j++) acc[i][j] = 0.f;

    for (int k0 = 0; k0 < Dout; k0 += 8) {
        float4 av = *(const float4*)&g_ctx[(row0 + ar) * Dout + k0 + ac];
        As[ac + 0][ar] = av.x;
        As[ac + 1][ar] = av.y;
        As[ac + 2][ar] = av.z;
        As[ac + 3][ar] = av.w;
        *(float4*)&Bs[br][bc] = *(const float4*)&Wo[(k0 + br) * Dout + col0 + bc];
        __syncthreads();

#pragma unroll
        for (int k = 0; k < 8; k++) {
            float4 a0 = *(float4*)&As[k][ty * 8];
            float4 a1 = *(float4*)&As[k][ty * 8 + 4];
            float4 b0 = *(float4*)&Bs[k][tx * 8];
            float4 b1 = *(float4*)&Bs[k][tx * 8 + 4];
            float a[8] = {a0.x, a0.y, a0.z, a0.w, a1.x, a1.y, a1.z, a1.w};
            float b[8] = {b0.x, b0.y, b0.z, b0.w, b1.x, b1.y, b1.z, b1.w};
#pragma unroll
            for (int i = 0; i < 8; i++)
#pragma unroll
                for (int j = 0; j < 8; j++) acc[i][j] = fmaf(a[i], b[j], acc[i][j]);
        }
        __syncthreads();
    }

#pragma unroll
    for (int i = 0; i < 8; i++) {
        int gm = row0 + ty * 8 + i;
#pragma unroll
        for (int j = 0; j < 8; j++) {
            int col = col0 + tx * 8 + j;
            out[gm * Dout + col] = acc[i][j] + bo[col];
        }
    }
}

// ---------------------------------------------------------------------------
// Flash attention (fp32, causal), PARALLEL softmax (4 threads/row).
// One block = 64-row q-block x head x batch, 256 threads, 4x4 tile each.
// smem (floats):
//   Qst [64k][68] @0, Kst [64k][68] @4352, Vs [64][64] @8704,
//   Ss [64][65] @12800, lrow @16960, rsc @17024, red @17088, red2 @17344
// ---------------------------------------------------------------------------
#define FLASH_SMEM_FLOATS 17600
#define FLASH_SMEM_BYTES  (FLASH_SMEM_FLOATS * 4)

__global__ __launch_bounds__(256) void flash_kernel()
{
    extern __shared__ float sm[];
    float* Qst  = sm;
    float* Kst  = sm + 4352;
    float* Vs   = sm + 8704;
    float* Ss   = sm + 12800;
    float* lrow = sm + 16960;
    float* rsc  = sm + 17024;
    float* red  = sm + 17088;   // [64][4] partial max
    float* red2 = sm + 17344;   // [64][4] partial sum

    const int tid = threadIdx.x;
    const int qb  = blockIdx.x;
    const int h   = blockIdx.y;
    const int b   = blockIdx.z;

    const float* Qp = g_q + (size_t)((b * Hh + h) * Nn + qb * 64) * HDd;
    const float* Kp = g_k + (size_t)(b * Hh + h) * Nn * HDd;
    const float* Vp = g_v + (size_t)(b * Hh + h) * Nn * HDd;

    const int lr = tid >> 4;         // 0..15
    const int lc = (tid & 15) * 4;   // 0..60
    const float sm_scale = 0.125f;   // 1/sqrt(64)

    // Load Q (transposed, pre-scaled)
#pragma unroll
    for (int rep = 0; rep < 4; rep++) {
        int r = lr + rep * 16;
        float4 v = *(const float4*)&Qp[r * HDd + lc];
        Qst[(lc + 0) * 68 + r] = v.x * sm_scale;
        Qst[(lc + 1) * 68 + r] = v.y * sm_scale;
        Qst[(lc + 2) * 68 + r] = v.z * sm_scale;
        Qst[(lc + 3) * 68 + r] = v.w * sm_scale;
    }

    const int ty = tid >> 4;
    const int tx = tid & 15;
    const int r0 = ty * 4;
    const int c0 = tx * 4;

    // softmax ownership: 4 threads per row, 16 cols each
    const int srow  = tid >> 2;           // 0..63
    const int sq    = tid & 3;            // 0..3
    const int sbase = srow * 65 + sq * 16;

    // running (m, l) for row `srow`, duplicated across its 4 owner threads
    float m_loc = -INFINITY;
    float l_loc = 0.f;

    float acc[4][4];
#pragma unroll
    for (int i = 0; i < 4; i++)
#pragma unroll
        for (int j = 0; j < 4; j++) acc[i][j] = 0.f;

    __syncthreads();

    for (int kb = 0; kb <= qb; kb++) {
        // Load K (transposed) and V (natural)
#pragma unroll
        for (int rep = 0; rep < 4; rep++) {
            int r = lr + rep * 16;
            float4 kv = *(const float4*)&Kp[(kb * 64 + r) * HDd + lc];
            Kst[(lc + 0) * 68 + r] = kv.x;
            Kst[(lc + 1) * 68 + r] = kv.y;
            Kst[(lc + 2) * 68 + r] = kv.z;
            Kst[(lc + 3) * 68 + r] = kv.w;
            *(float4*)&Vs[r * 64 + lc] = *(const float4*)&Vp[(kb * 64 + r) * HDd + lc];
        }
        __syncthreads();

        // S = Q K^T (4x4 per thread)
        float sacc[4][4];
#pragma unroll
        for (int i = 0; i < 4; i++)
#pragma unroll
            for (int j = 0; j < 4; j++) sacc[i][j] = 0.f;

#pragma unroll 8
        for (int k = 0; k < 64; k++) {
            float4 a = *(float4*)&Qst[k * 68 + r0];
            float4 bb = *(float4*)&Kst[k * 68 + c0];
            float av[4] = {a.x, a.y, a.z, a.w};
            float bv[4] = {bb.x, bb.y, bb.z, bb.w};
#pragma unroll
            for (int i = 0; i < 4; i++)
#pragma unroll
                for (int j = 0; j < 4; j++) sacc[i][j] = fmaf(av[i], bv[j], sacc[i][j]);
        }

        // Causal mask on the diagonal block, write to Ss
        const bool diag = (kb == qb);
#pragma unroll
        for (int i = 0; i < 4; i++)
#pragma unroll
            for (int j = 0; j < 4; j++) {
                float s = sacc[i][j];
                if (diag && (c0 + j > r0 + i)) s = -1e30f;
                Ss[(r0 + i) * 65 + (c0 + j)] = s;
            }
        __syncthreads();

        // --- Parallel softmax: pass 1, partial max over 16 cols ---
        {
            float mx = -1e30f;
#pragma unroll
            for (int j = 0; j < 16; j++) mx = fmaxf(mx, Ss[sbase + j]);
            red[srow * 4 + sq] = mx;
        }
        __syncthreads();

        // All 4 owners of a row compute the same new max / rescale
        float sc;
        {
            float m4 = fmaxf(fmaxf(red[srow * 4 + 0], red[srow * 4 + 1]),
                             fmaxf(red[srow * 4 + 2], red[srow * 4 + 3]));
            float mnew = fmaxf(m_loc, m4);
            sc = __expf(m_loc - mnew);
            m_loc = mnew;
            if (sq == 0) rsc[srow] = sc;

            // pass 2: exponentiate 16 cols, partial sum
            float s = 0.f;
#pragma unroll
            for (int j = 0; j < 16; j++) {
                float p = __expf(Ss[sbase + j] - mnew);
                Ss[sbase + j] = p;
                s += p;
            }
            red2[srow * 4 + sq] = s;
        }
        __syncthreads();

        // l update (all 4 owners identically; sq==0 publishes for the epilogue)
        {
            float s4 = (red2[srow * 4 + 0] + red2[srow * 4 + 1]) +
                       (red2[srow * 4 + 2] + red2[srow * 4 + 3]);
            l_loc = l_loc * sc + s4;
            if (sq == 0) lrow[srow] = l_loc;
        }

        // Rescale accumulator, then O += P @ V
#pragma unroll
        for (int i = 0; i < 4; i++) {
            float scr = rsc[r0 + i];
#pragma unroll
            for (int j = 0; j < 4; j++) acc[i][j] *= scr;
        }
#pragma unroll 8
        for (int j = 0; j < 64; j++) {
            float4 vv = *(float4*)&Vs[j * 64 + c0];
            float vvv[4] = {vv.x, vv.y, vv.z, vv.w};
#pragma unroll
            for (int i = 0; i < 4; i++) {
                float p = Ss[(r0 + i) * 65 + j];
#pragma unroll
                for (int jj = 0; jj < 4; jj++) acc[i][jj] = fmaf(p, vvv[jj], acc[i][jj]);
            }
        }
        __syncthreads();
    }

    // Normalize and write ctx in [B,N,D]
#pragma unroll
    for (int i = 0; i < 4; i++) {
        float inv = 1.f / lrow[r0 + i];
        int n = qb * 64 + r0 + i;
        float4 o;
        o.x = acc[i][0] * inv;
        o.y = acc[i][1] * inv;
        o.z = acc[i][2] * inv;
        o.w = acc[i][3] * inv;
        *(float4*)&g_ctx[(size_t)(b * Nn + n) * Dout + h * 64 + c0] = o;
    }
}

// ---------------------------------------------------------------------------
extern "C" void kernel_launch(void* const* d_in, const int* in_sizes, int n_in,
                              void* d_out, int out_size)
{
    const float* x  = (const float*)d_in[0];
    const float* Wq = (const float*)d_in[1];
    const float* Wk = (const float*)d_in[2];
    const float* Wv = (const float*)d_in[3];
    const float* Wo = (const float*)d_in[4];
    const float* bo = (const float*)d_in[5];
    float* out = (float*)d_out;

    cudaFuncSetAttribute(flash_kernel, cudaFuncAttributeMaxDynamicSharedMemorySize,
                         FLASH_SMEM_BYTES);

    dim3 gemm_grid(Dout / 128, (Bb * Nn) / 128, 3);
    qkv_kernel<<<gemm_grid, 256>>>(x, Wq, Wk, Wv);

    dim3 flash_grid(Nn / 64, Hh, Bb);
    flash_kernel<<<flash_grid, 256, FLASH_SMEM_BYTES>>>();

    dim3 out_grid(Dout / 128, (Bb * Nn) / 128);
    out_proj_kernel<<<out_grid, 256>>>(Wo, bo, out);
}

// round 13
// speedup vs baseline: 1.0549x; 1.0430x over previous
#include <cuda_runtime.h>
#include <math.h>

// Problem constants
#define Bb   2
#define Nn   2048
#define Din  1024
#define Dout 1024
#define Hh   16
#define HDd  64

// Scratch (allocation-free rule: __device__ globals) — identical set to R1
__device__ float g_q[Bb * Hh * Nn * HDd];     // [B,H,N,HD]
__device__ float g_k[Bb * Hh * Nn * HDd];
__device__ float g_v[Bb * Hh * Nn * HDd];
__device__ float g_ctx[Bb * Nn * Dout];       // [B,N,D] row-major

// ---------------------------------------------------------------------------
// 128x128x8 SGEMM body, 256 threads, 8x8 microtile per thread. (R1 verbatim —
// measured at ~97% of the FFMA-3reg issue ceiling; do not touch.)
// ---------------------------------------------------------------------------
__global__ __launch_bounds__(256) void qkv_kernel(
    const float* __restrict__ x,
    const float* __restrict__ Wq,
    const float* __restrict__ Wk,
    const float* __restrict__ Wv)
{
    __shared__ float As[8][128];
    __shared__ float Bs[8][128];

    const float* W   = (blockIdx.z == 0) ? Wq : (blockIdx.z == 1) ? Wk : Wv;
    float*       out = (blockIdx.z == 0) ? g_q : (blockIdx.z == 1) ? g_k : g_v;

    const int tid  = threadIdx.x;
    const int row0 = blockIdx.y * 128;
    const int col0 = blockIdx.x * 128;

    const int ar = tid >> 1;
    const int ac = (tid & 1) * 4;
    const int br = tid >> 5;
    const int bc = (tid & 31) * 4;
    const int ty = tid >> 4;
    const int tx = tid & 15;

    float acc[8][8];
#pragma unroll
    for (int i = 0; i < 8; i++)
#pragma unroll
        for (int j = 0; j < 8; j++) acc[i][j] = 0.f;

    for (int k0 = 0; k0 < Din; k0 += 8) {
        float4 av = *(const float4*)&x[(row0 + ar) * Din + k0 + ac];
        As[ac + 0][ar] = av.x;
        As[ac + 1][ar] = av.y;
        As[ac + 2][ar] = av.z;
        As[ac + 3][ar] = av.w;
        *(float4*)&Bs[br][bc] = *(const float4*)&W[(k0 + br) * Dout + col0 + bc];
        __syncthreads();

#pragma unroll
        for (int k = 0; k < 8; k++) {
            float4 a0 = *(float4*)&As[k][ty * 8];
            float4 a1 = *(float4*)&As[k][ty * 8 + 4];
            float4 b0 = *(float4*)&Bs[k][tx * 8];
            float4 b1 = *(float4*)&Bs[k][tx * 8 + 4];
            float a[8] = {a0.x, a0.y, a0.z, a0.w, a1.x, a1.y, a1.z, a1.w};
            float b[8] = {b0.x, b0.y, b0.z, b0.w, b1.x, b1.y, b1.z, b1.w};
#pragma unroll
            for (int i = 0; i < 8; i++)
#pragma unroll
                for (int j = 0; j < 8; j++) acc[i][j] = fmaf(a[i], b[j], acc[i][j]);
        }
        __syncthreads();
    }

#pragma unroll
    for (int i = 0; i < 8; i++) {
        int gm = row0 + ty * 8 + i;
        int b  = gm >> 11;
        int n  = gm & 2047;
#pragma unroll
        for (int j = 0; j < 8; j++) {
            int col = col0 + tx * 8 + j;
            int h   = col >> 6;
            int hd  = col & 63;
            out[((b * Hh + h) * Nn + n) * HDd + hd] = acc[i][j];
        }
    }
}

__global__ __launch_bounds__(256) void out_proj_kernel(
    const float* __restrict__ Wo,
    const float* __restrict__ bo,
    float* __restrict__ out)
{
    __shared__ float As[8][128];
    __shared__ float Bs[8][128];

    const int tid  = threadIdx.x;
    const int row0 = blockIdx.y * 128;
    const int col0 = blockIdx.x * 128;

    const int ar = tid >> 1;
    const int ac = (tid & 1) * 4;
    const int br = tid >> 5;
    const int bc = (tid & 31) * 4;
    const int ty = tid >> 4;
    const int tx = tid & 15;

    float acc[8][8];
#pragma unroll
    for (int i = 0; i < 8; i++)
#pragma unroll
        for (int j = 0; j < 8; j++) acc[i][j] = 0.f;

    for (int k0 = 0; k0 < Dout; k0 += 8) {
        float4 av = *(const float4*)&g_ctx[(row0 + ar) * Dout + k0 + ac];
        As[ac + 0][ar] = av.x;
        As[ac + 1][ar] = av.y;
        As[ac + 2][ar] = av.z;
        As[ac + 3][ar] = av.w;
        *(float4*)&Bs[br][bc] = *(const float4*)&Wo[(k0 + br) * Dout + col0 + bc];
        __syncthreads();

#pragma unroll
        for (int k = 0; k < 8; k++) {
            float4 a0 = *(float4*)&As[k][ty * 8];
            float4 a1 = *(float4*)&As[k][ty * 8 + 4];
            float4 b0 = *(float4*)&Bs[k][tx * 8];
            float4 b1 = *(float4*)&Bs[k][tx * 8 + 4];
            float a[8] = {a0.x, a0.y, a0.z, a0.w, a1.x, a1.y, a1.z, a1.w};
            float b[8] = {b0.x, b0.y, b0.z, b0.w, b1.x, b1.y, b1.z, b1.w};
#pragma unroll
            for (int i = 0; i < 8; i++)
#pragma unroll
                for (int j = 0; j < 8; j++) acc[i][j] = fmaf(a[i], b[j], acc[i][j]);
        }
        __syncthreads();
    }

#pragma unroll
    for (int i = 0; i < 8; i++) {
        int gm = row0 + ty * 8 + i;
#pragma unroll
        for (int j = 0; j < 8; j++) {
            int col = col0 + tx * 8 + j;
            out[gm * Dout + col] = acc[i][j] + bo[col];
        }
    }
}

// ---------------------------------------------------------------------------
// Flash attention (fp32, causal), register softmax via half-warp shuffles.
// One block = 64-row q-block x head x batch, 256 threads, 4x4 tile each.
// qb reversed (longest blocks launch first) for tail packing.
// Row r0+i is owned by the 16 lanes sharing ty -> shfl.xor {1,2,4,8} reduces
// max/sum without block barriers; m,l live in registers (replicated x16).
// smem (floats): Qst[64k][68] @0, Kst[64k][68] @4352, Vs[64][64] @8704,
//                Ss[64 r][68] @12800  (stride 68 -> 16B-aligned float4 rows)
// ---------------------------------------------------------------------------
#define FLASH_SMEM_FLOATS 17152
#define FLASH_SMEM_BYTES  (FLASH_SMEM_FLOATS * 4)

__global__ __launch_bounds__(256) void flash_kernel()
{
    extern __shared__ float sm[];
    float* Qst = sm;            // [k][r] stride 68
    float* Kst = sm + 4352;     // [k][c] stride 68
    float* Vs  = sm + 8704;     // [j][c] 64x64
    float* Ss  = sm + 12800;    // [r][j] stride 68

    const int tid = threadIdx.x;
    const int qb  = (int)gridDim.x - 1 - (int)blockIdx.x;   // longest first
    const int h   = blockIdx.y;
    const int b   = blockIdx.z;

    const float* Qp = g_q + (size_t)((b * Hh + h) * Nn + qb * 64) * HDd;
    const float* Kp = g_k + (size_t)(b * Hh + h) * Nn * HDd;
    const float* Vp = g_v + (size_t)(b * Hh + h) * Nn * HDd;

    const int lr = tid >> 4;         // 0..15
    const int lc = (tid & 15) * 4;   // 0..60
    const float sm_scale = 0.125f;   // 1/sqrt(64)

    // Load Q (transposed, pre-scaled)
#pragma unroll
    for (int rep = 0; rep < 4; rep++) {
        int r = lr + rep * 16;
        float4 v = *(const float4*)&Qp[r * HDd + lc];
        Qst[(lc + 0) * 68 + r] = v.x * sm_scale;
        Qst[(lc + 1) * 68 + r] = v.y * sm_scale;
        Qst[(lc + 2) * 68 + r] = v.z * sm_scale;
        Qst[(lc + 3) * 68 + r] = v.w * sm_scale;
    }

    const int ty = tid >> 4;
    const int tx = tid & 15;
    const int r0 = ty * 4;
    const int c0 = tx * 4;

    float m_loc[4], l_loc[4];
#pragma unroll
    for (int i = 0; i < 4; i++) { m_loc[i] = -INFINITY; l_loc[i] = 0.f; }

    float acc[4][4];
#pragma unroll
    for (int i = 0; i < 4; i++)
#pragma unroll
        for (int j = 0; j < 4; j++) acc[i][j] = 0.f;

    __syncthreads();

    for (int kb = 0; kb <= qb; kb++) {
        // Load K (transposed) and V (natural)
#pragma unroll
        for (int rep = 0; rep < 4; rep++) {
            int r = lr + rep * 16;
            float4 kv = *(const float4*)&Kp[(kb * 64 + r) * HDd + lc];
            Kst[(lc + 0) * 68 + r] = kv.x;
            Kst[(lc + 1) * 68 + r] = kv.y;
            Kst[(lc + 2) * 68 + r] = kv.z;
            Kst[(lc + 3) * 68 + r] = kv.w;
            *(float4*)&Vs[r * 64 + lc] = *(const float4*)&Vp[(kb * 64 + r) * HDd + lc];
        }
        __syncthreads();

        // S = Q K^T (4x4 per thread)
        float sacc[4][4];
#pragma unroll
        for (int i = 0; i < 4; i++)
#pragma unroll
            for (int j = 0; j < 4; j++) sacc[i][j] = 0.f;

#pragma unroll 8
        for (int k = 0; k < 64; k++) {
            float4 a = *(float4*)&Qst[k * 68 + r0];
            float4 bb = *(float4*)&Kst[k * 68 + c0];
            float av[4] = {a.x, a.y, a.z, a.w};
            float bv[4] = {bb.x, bb.y, bb.z, bb.w};
#pragma unroll
            for (int i = 0; i < 4; i++)
#pragma unroll
                for (int j = 0; j < 4; j++) sacc[i][j] = fmaf(av[i], bv[j], sacc[i][j]);
        }

        // Causal mask on the diagonal block (in registers)
        if (kb == qb) {
#pragma unroll
            for (int i = 0; i < 4; i++)
#pragma unroll
                for (int j = 0; j < 4; j++)
                    if (c0 + j > r0 + i) sacc[i][j] = -1e30f;
        }

        // Register softmax: per row, shuffle-reduce max & sum over 16 lanes
#pragma unroll
        for (int i = 0; i < 4; i++) {
            float rm = fmaxf(fmaxf(sacc[i][0], sacc[i][1]),
                             fmaxf(sacc[i][2], sacc[i][3]));
            rm = fmaxf(rm, __shfl_xor_sync(0xffffffffu, rm, 1));
            rm = fmaxf(rm, __shfl_xor_sync(0xffffffffu, rm, 2));
            rm = fmaxf(rm, __shfl_xor_sync(0xffffffffu, rm, 4));
            rm = fmaxf(rm, __shfl_xor_sync(0xffffffffu, rm, 8));

            float mnew = fmaxf(m_loc[i], rm);
            float scr  = __expf(m_loc[i] - mnew);
            m_loc[i] = mnew;

            float p0 = __expf(sacc[i][0] - mnew);
            float p1 = __expf(sacc[i][1] - mnew);
            float p2 = __expf(sacc[i][2] - mnew);
            float p3 = __expf(sacc[i][3] - mnew);
            float4 pv; pv.x = p0; pv.y = p1; pv.z = p2; pv.w = p3;
            *(float4*)&Ss[(r0 + i) * 68 + c0] = pv;

            float ps = (p0 + p1) + (p2 + p3);
            ps += __shfl_xor_sync(0xffffffffu, ps, 1);
            ps += __shfl_xor_sync(0xffffffffu, ps, 2);
            ps += __shfl_xor_sync(0xffffffffu, ps, 4);
            ps += __shfl_xor_sync(0xffffffffu, ps, 8);
            l_loc[i] = l_loc[i] * scr + ps;

#pragma unroll
            for (int j = 0; j < 4; j++) acc[i][j] *= scr;
        }
        __syncwarp();   // P rows for group ty are written & read by the same warp

        // O += P @ V (float4 P loads, stride 68)
#pragma unroll 4
        for (int j4 = 0; j4 < 64; j4 += 4) {
            float4 v0 = *(float4*)&Vs[(j4 + 0) * 64 + c0];
            float4 v1 = *(float4*)&Vs[(j4 + 1) * 64 + c0];
            float4 v2 = *(float4*)&Vs[(j4 + 2) * 64 + c0];
            float4 v3 = *(float4*)&Vs[(j4 + 3) * 64 + c0];
#pragma unroll
            for (int i = 0; i < 4; i++) {
                float4 p = *(float4*)&Ss[(r0 + i) * 68 + j4];
                acc[i][0] = fmaf(p.x, v0.x, acc[i][0]);
                acc[i][1] = fmaf(p.x, v0.y, acc[i][1]);
                acc[i][2] = fmaf(p.x, v0.z, acc[i][2]);
                acc[i][3] = fmaf(p.x, v0.w, acc[i][3]);
                acc[i][0] = fmaf(p.y, v1.x, acc[i][0]);
                acc[i][1] = fmaf(p.y, v1.y, acc[i][1]);
                acc[i][2] = fmaf(p.y, v1.z, acc[i][2]);
                acc[i][3] = fmaf(p.y, v1.w, acc[i][3]);
                acc[i][0] = fmaf(p.z, v2.x, acc[i][0]);
                acc[i][1] = fmaf(p.z, v2.y, acc[i][1]);
                acc[i][2] = fmaf(p.z, v2.z, acc[i][2]);
                acc[i][3] = fmaf(p.z, v2.w, acc[i][3]);
                acc[i][0] = fmaf(p.w, v3.x, acc[i][0]);
                acc[i][1] = fmaf(p.w, v3.y, acc[i][1]);
                acc[i][2] = fmaf(p.w, v3.z, acc[i][2]);
                acc[i][3] = fmaf(p.w, v3.w, acc[i][3]);
            }
        }
        __syncthreads();
    }

    // Normalize and write ctx in [B,N,D]
#pragma unroll
    for (int i = 0; i < 4; i++) {
        float inv = 1.f / l_loc[i];
        int n = qb * 64 + r0 + i;
        float4 o;
        o.x = acc[i][0] * inv;
        o.y = acc[i][1] * inv;
        o.z = acc[i][2] * inv;
        o.w = acc[i][3] * inv;
        *(float4*)&g_ctx[(size_t)(b * Nn + n) * Dout + h * 64 + c0] = o;
    }
}

// ---------------------------------------------------------------------------
extern "C" void kernel_launch(void* const* d_in, const int* in_sizes, int n_in,
                              void* d_out, int out_size)
{
    const float* x  = (const float*)d_in[0];
    const float* Wq = (const float*)d_in[1];
    const float* Wk = (const float*)d_in[2];
    const float* Wv = (const float*)d_in[3];
    const float* Wo = (const float*)d_in[4];
    const float* bo = (const float*)d_in[5];
    float* out = (float*)d_out;

    cudaFuncSetAttribute(flash_kernel, cudaFuncAttributeMaxDynamicSharedMemorySize,
                         FLASH_SMEM_BYTES);

    dim3 gemm_grid(Dout / 128, (Bb * Nn) / 128, 3);
    qkv_kernel<<<gemm_grid, 256>>>(x, Wq, Wk, Wv);

    dim3 flash_grid(Nn / 64, Hh, Bb);
    flash_kernel<<<flash_grid, 256, FLASH_SMEM_BYTES>>>();

    dim3 out_grid(Dout / 128, (Bb * Nn) / 128);
    out_proj_kernel<<<out_grid, 256>>>(Wo, bo, out);
}